// round 1
// baseline (speedup 1.0000x reference)
#include <cuda_runtime.h>
#include <cstdint>

#define N_NODES 4096
#define OUTF 256
#define NH 8
#define TI 16
#define JC 32

typedef unsigned long long u64;

// Scratch (device globals — no allocation allowed)
__device__ float  g_buf[N_NODES * OUTF];          // g = h @ W^T, [n][h*32+f]
__device__ float4 PL_buf[N_NODES * NH];           // {s_i, exp(s_i), exp(0.2 s_i), 0}
__device__ float4 PR_buf[N_NODES * NH];           // {s_j, exp(s_j), exp(0.2 s_j), 0}

#define PACK2(d, lo, hi) asm("mov.b64 %0, {%1, %2};" : "=l"(d) : "r"(lo), "r"(hi))
#define FMA2(d, a, b, c) asm("fma.rn.f32x2 %0, %1, %2, %3;" : "=l"(d) : "l"(a), "l"(b), "l"(c))

// ---------------------------------------------------------------------------
// Kernel 1: g = h @ W^T   (4096x256 @ 256x256)
// ---------------------------------------------------------------------------
__global__ __launch_bounds__(256) void gemm_kernel(const float* __restrict__ H,
                                                   const float* __restrict__ W) {
    __shared__ float hs[64][32];
    __shared__ float ws[32][68];
    int t  = threadIdx.x;
    int bo = blockIdx.x;   // output-feature tile (0..3)
    int bn = blockIdx.y;   // node tile (0..63)
    int tx = t & 15, ty = t >> 4;
    float acc[4][4] = {};

    int r = t >> 3, c = (t & 7) << 2;
    for (int k0 = 0; k0 < 256; k0 += 32) {
#pragma unroll
        for (int rr = 0; rr < 64; rr += 32) {
            float4 v = *(const float4*)&H[(bn * 64 + r + rr) * 256 + k0 + c];
            *(float4*)&hs[r + rr][c] = v;
        }
#pragma unroll
        for (int oo = 0; oo < 64; oo += 32) {
            float4 v = *(const float4*)&W[(bo * 64 + r + oo) * 256 + k0 + c];
            ws[c + 0][r + oo] = v.x; ws[c + 1][r + oo] = v.y;
            ws[c + 2][r + oo] = v.z; ws[c + 3][r + oo] = v.w;
        }
        __syncthreads();
#pragma unroll
        for (int k = 0; k < 32; k++) {
            float4 bv = *(const float4*)&ws[k][tx * 4];
            const float* bp = &bv.x;
            float av[4];
#pragma unroll
            for (int i = 0; i < 4; i++) av[i] = hs[ty * 4 + i][k];
#pragma unroll
            for (int i = 0; i < 4; i++)
#pragma unroll
                for (int j = 0; j < 4; j++)
                    acc[i][j] = fmaf(av[i], bp[j], acc[i][j]);
        }
        __syncthreads();
    }
#pragma unroll
    for (int i = 0; i < 4; i++) {
        float4 v = make_float4(acc[i][0], acc[i][1], acc[i][2], acc[i][3]);
        *(float4*)&g_buf[(bn * 64 + ty * 4 + i) * 256 + bo * 64 + tx * 4] = v;
    }
}

// ---------------------------------------------------------------------------
// Kernel 2: per-node scores s_i, s_j and their exponentials.
// One warp per node; lanes cover the 32 hidden features of each head.
// ---------------------------------------------------------------------------
__global__ __launch_bounds__(256) void score_kernel(const float* __restrict__ a) {
    int gw   = (blockIdx.x * 256 + threadIdx.x) >> 5;
    int lane = threadIdx.x & 31;
    if (gw >= N_NODES) return;
    float al = a[lane], ar = a[32 + lane];
#pragma unroll
    for (int h = 0; h < NH; h++) {
        float gv = g_buf[gw * 256 + h * 32 + lane];
        float sl = gv * al, sr = gv * ar;
#pragma unroll
        for (int o = 16; o > 0; o >>= 1) {
            sl += __shfl_xor_sync(0xffffffffu, sl, o);
            sr += __shfl_xor_sync(0xffffffffu, sr, o);
        }
        if (lane == 0) {
            PL_buf[gw * NH + h] = make_float4(sl, expf(sl), expf(0.2f * sl), 0.f);
            PR_buf[gw * NH + h] = make_float4(sr, expf(sr), expf(0.2f * sr), 0.f);
        }
    }
}

// ---------------------------------------------------------------------------
// Kernel 3: fused masked-softmax attention + aggregation.
// Block owns TI=16 destination rows (all 8 heads, all 32 features).
// Per 32-j chunk: stage A loads adjacency, stage B builds unnormalized
// softmax weights w (no exp — separable trick) into shared, stage C does
// packed f32x2 FMAs streaming g from L2. Normalize by Z at the end.
// ---------------------------------------------------------------------------
__global__ __launch_bounds__(256) void attn_kernel(const int* __restrict__ adj,
                                                   float* __restrict__ out) {
    __shared__ float  w_sh[JC][NH][20];   // [jj][h][i], padded to 20 for banks
    __shared__ int    adj_sh[TI][JC];
    __shared__ float  z_sh[TI][NH];
    __shared__ float4 pl_sh[TI][NH];

    int t  = threadIdx.x;
    int i0 = blockIdx.x * TI;

    if (t < TI * NH) {
        ((float4*)pl_sh)[t] = PL_buf[i0 * NH + t];
        ((float*)z_sh)[t]   = 0.f;
    }

    int hB = t & 7, jjB = t >> 3;      // stage-B mapping: one (jj,h) slot/thread
    int hC = t >> 5, lane = t & 31;    // stage-C mapping: warp = head, lane = f

    float zp[TI];
#pragma unroll
    for (int i = 0; i < TI; i++) zp[i] = 0.f;
    u64 acc[8];                        // acc[k] = {out[2k][f], out[2k+1][f]}
#pragma unroll
    for (int k = 0; k < 8; k++) acc[k] = 0ull;

    __syncthreads();

    for (int j0 = 0; j0 < N_NODES; j0 += JC) {
        // stage A: adjacency tile (each adj element read exactly once per block)
        {
            int r = t >> 4, c = t & 15;
            adj_sh[r][c]      = adj[(i0 + r) * N_NODES + j0 + c];
            adj_sh[r][c + 16] = adj[(i0 + r) * N_NODES + j0 + c + 16];
        }
        __syncthreads();

        // stage B: w[jj][h][i] = adj ? (s_i+s_j>0 ? E_i*E_j : F_i*F_j) : 0
        {
            float4 pr = PR_buf[(j0 + jjB) * NH + hB];
#pragma unroll
            for (int i = 0; i < TI; i++) {
                float4 pl = pl_sh[i][hB];
                float w = 0.f;
                if (adj_sh[i][jjB] != 0)
                    w = (pl.x + pr.x > 0.f) ? pl.y * pr.y : pl.z * pr.z;
                zp[i] += w;
                w_sh[jjB][hB][i] = w;
            }
        }
        __syncthreads();

        // stage C: acc[i pair] += {g,g} * {w[2k], w[2k+1]}   (fma.rn.f32x2)
        {
            const float* grow = &g_buf[j0 * 256 + hC * 32 + lane];
#pragma unroll 4
            for (int jj = 0; jj < JC; jj++) {
                unsigned int gu = __float_as_uint(grow[jj * 256]);
                u64 gd; PACK2(gd, gu, gu);
                const u64* wr = (const u64*)&w_sh[jj][hC][0];
#pragma unroll
                for (int k = 0; k < 8; k++) FMA2(acc[k], gd, wr[k], acc[k]);
            }
        }
        __syncthreads();   // protect w_sh/adj_sh for next chunk
    }

    // reduce softmax denominators across the 32 threads sharing each head
#pragma unroll
    for (int i = 0; i < TI; i++) atomicAdd(&z_sh[i][hB], zp[i]);
    __syncthreads();

#pragma unroll
    for (int k = 0; k < 8; k++) {
        float2 v = *(float2*)&acc[k];
        int ia = 2 * k, ib = 2 * k + 1;
        out[(i0 + ia) * 256 + hC * 32 + lane] = v.x / z_sh[ia][hC];
        out[(i0 + ib) * 256 + hC * 32 + lane] = v.y / z_sh[ib][hC];
    }
}

// ---------------------------------------------------------------------------
extern "C" void kernel_launch(void* const* d_in, const int* in_sizes, int n_in,
                              void* d_out, int out_size) {
    const float* H   = (const float*)d_in[0];
    const float* W   = (const float*)d_in[1];
    const float* a   = (const float*)d_in[2];
    const int*   adj = (const int*)d_in[3];
    float*       out = (float*)d_out;

    dim3 gg(OUTF / 64, N_NODES / 64);
    gemm_kernel<<<gg, 256>>>(H, W);
    score_kernel<<<N_NODES / 8, 256>>>(a);
    attn_kernel<<<N_NODES / TI, 256>>>(adj, out);
}

// round 3
// speedup vs baseline: 1.2416x; 1.2416x over previous
#include <cuda_runtime.h>
#include <cstdint>

#define N_NODES 4096
#define OUTF 256
#define NH 8
#define TI 16
#define JC 32

typedef unsigned long long u64;

// Scratch (device globals — no allocation allowed)
__device__ float  g_buf[N_NODES * OUTF];          // g = h @ W^T, [n][h*32+f]
__device__ float4 PL_buf[N_NODES * NH];           // {s_i, exp(s_i), exp(0.2 s_i), 0}
__device__ float4 PR_buf[N_NODES * NH];           // {s_j, exp(s_j), exp(0.2 s_j), 0}

#define PACK2(d, lo, hi) asm("mov.b64 %0, {%1, %2};" : "=l"(d) : "r"(lo), "r"(hi))
#define FMA2(d, a, b, c) asm("fma.rn.f32x2 %0, %1, %2, %3;" : "=l"(d) : "l"(a), "l"(b), "l"(c))
#define LDSV2(a, b, addr) asm volatile("ld.shared.v2.b64 {%0,%1},[%2];" : "=l"(a), "=l"(b) : "r"(addr))

// ---------------------------------------------------------------------------
// Kernel 1: g = h @ W^T   (4096x256 @ 256x256)
// ---------------------------------------------------------------------------
__global__ __launch_bounds__(256) void gemm_kernel(const float* __restrict__ H,
                                                   const float* __restrict__ W) {
    __shared__ float hs[64][32];
    __shared__ float ws[32][68];
    int t  = threadIdx.x;
    int bo = blockIdx.x;   // output-feature tile (0..3)
    int bn = blockIdx.y;   // node tile (0..63)
    int tx = t & 15, ty = t >> 4;
    float acc[4][4] = {};

    int r = t >> 3, c = (t & 7) << 2;
    for (int k0 = 0; k0 < 256; k0 += 32) {
#pragma unroll
        for (int rr = 0; rr < 64; rr += 32) {
            float4 v = *(const float4*)&H[(bn * 64 + r + rr) * 256 + k0 + c];
            *(float4*)&hs[r + rr][c] = v;
        }
#pragma unroll
        for (int oo = 0; oo < 64; oo += 32) {
            float4 v = *(const float4*)&W[(bo * 64 + r + oo) * 256 + k0 + c];
            ws[c + 0][r + oo] = v.x; ws[c + 1][r + oo] = v.y;
            ws[c + 2][r + oo] = v.z; ws[c + 3][r + oo] = v.w;
        }
        __syncthreads();
#pragma unroll
        for (int k = 0; k < 32; k++) {
            float4 bv = *(const float4*)&ws[k][tx * 4];
            const float* bp = &bv.x;
            float av[4];
#pragma unroll
            for (int i = 0; i < 4; i++) av[i] = hs[ty * 4 + i][k];
#pragma unroll
            for (int i = 0; i < 4; i++)
#pragma unroll
                for (int j = 0; j < 4; j++)
                    acc[i][j] = fmaf(av[i], bp[j], acc[i][j]);
        }
        __syncthreads();
    }
#pragma unroll
    for (int i = 0; i < 4; i++) {
        float4 v = make_float4(acc[i][0], acc[i][1], acc[i][2], acc[i][3]);
        *(float4*)&g_buf[(bn * 64 + ty * 4 + i) * 256 + bo * 64 + tx * 4] = v;
    }
}

// ---------------------------------------------------------------------------
// Kernel 2: per-node scores s_i, s_j and their exponentials.
// ---------------------------------------------------------------------------
__global__ __launch_bounds__(256) void score_kernel(const float* __restrict__ a) {
    int gw   = (blockIdx.x * 256 + threadIdx.x) >> 5;
    int lane = threadIdx.x & 31;
    if (gw >= N_NODES) return;
    float al = a[lane], ar = a[32 + lane];
#pragma unroll
    for (int h = 0; h < NH; h++) {
        float gv = g_buf[gw * 256 + h * 32 + lane];
        float sl = gv * al, sr = gv * ar;
#pragma unroll
        for (int o = 16; o > 0; o >>= 1) {
            sl += __shfl_xor_sync(0xffffffffu, sl, o);
            sr += __shfl_xor_sync(0xffffffffu, sr, o);
        }
        if (lane == 0) {
            PL_buf[gw * NH + h] = make_float4(sl, expf(sl), expf(0.2f * sl), 0.f);
            PR_buf[gw * NH + h] = make_float4(sr, expf(sr), expf(0.2f * sr), 0.f);
        }
    }
}

// ---------------------------------------------------------------------------
// Kernel 3: fused masked-softmax attention + aggregation.
// Per 32-j chunk: prefetch g (LDGs fully hidden under stage A/B + barriers),
// stage A loads adjacency, stage B builds unnormalized softmax weights
// (separable exp trick, no MUFU), stage C does packed f32x2 FMAs with wide
// 128-bit broadcast shared loads of w. Normalize by Z at the end.
// ---------------------------------------------------------------------------
__global__ __launch_bounds__(256, 2) void attn_kernel(const int* __restrict__ adj,
                                                      float* __restrict__ out) {
    __shared__ float  w_sh[JC][NH][20];   // [jj][h][i], padded to 20 (16B-aligned rows)
    __shared__ int    adj_sh[TI][JC];
    __shared__ float  z_sh[TI][NH];
    __shared__ float4 pl_sh[TI][NH];

    int t  = threadIdx.x;
    int i0 = blockIdx.x * TI;

    if (t < TI * NH) {
        ((float4*)pl_sh)[t] = PL_buf[i0 * NH + t];
        ((float*)z_sh)[t]   = 0.f;
    }

    int hB = t & 7, jjB = t >> 3;      // stage-B mapping
    int hC = t >> 5, lane = t & 31;    // stage-C mapping: warp = head, lane = f

    float zp[TI];
#pragma unroll
    for (int i = 0; i < TI; i++) zp[i] = 0.f;
    u64 acc[8];
#pragma unroll
    for (int k = 0; k < 8; k++) acc[k] = 0ull;

    const float* grow = &g_buf[hC * 32 + lane];
    unsigned ws_base = (unsigned)__cvta_generic_to_shared(&w_sh[0][hC][0]);
    const int adjr = (t >> 4), adjc = (t & 15) * 2;
    const int* adj_src = &adj[(i0 + adjr) * N_NODES + adjc];
    const float4* pr_src = &PR_buf[jjB * NH + hB];

    __syncthreads();

    for (int j0 = 0; j0 < N_NODES; j0 += JC) {
        // Prefetch: g values for this chunk + PR for stage B. These LDGs are
        // independent of shared state; their L2 latency hides under stage A/B.
        float gpre[JC];
#pragma unroll
        for (int jj = 0; jj < JC; jj++) gpre[jj] = grow[(j0 + jj) * 256];
        float4 pr = pr_src[j0 * NH / 4 * 4 / 4];   // = PR_buf[(j0+jjB)*NH+hB]
        pr = PR_buf[(j0 + jjB) * NH + hB];

        // stage A: adjacency tile
        *(int2*)&adj_sh[adjr][adjc] = *(const int2*)&adj_src[j0];
        __syncthreads();

        // stage B: w[jj][h][i] = adj ? (s_i+s_j>0 ? E_i*E_j : F_i*F_j) : 0
#pragma unroll
        for (int i = 0; i < TI; i++) {
            float4 pl = pl_sh[i][hB];
            float w = 0.f;
            if (adj_sh[i][jjB] != 0)
                w = (pl.x + pr.x > 0.f) ? pl.y * pr.y : pl.z * pr.z;
            zp[i] += w;
            w_sh[jjB][hB][i] = w;
        }
        __syncthreads();

        // stage C: acc[k] += {g,g} * {w[2k], w[2k+1]}   (fma.rn.f32x2)
#pragma unroll
        for (int jj = 0; jj < JC; jj++) {
            unsigned gu = __float_as_uint(gpre[jj]);
            u64 gd; PACK2(gd, gu, gu);
            unsigned wa = ws_base + jj * (NH * 20 * 4);
            u64 w0, w1, w2, w3, w4, w5, w6, w7;
            LDSV2(w0, w1, wa);
            LDSV2(w2, w3, wa + 16);
            LDSV2(w4, w5, wa + 32);
            LDSV2(w6, w7, wa + 48);
            FMA2(acc[0], gd, w0, acc[0]);
            FMA2(acc[1], gd, w1, acc[1]);
            FMA2(acc[2], gd, w2, acc[2]);
            FMA2(acc[3], gd, w3, acc[3]);
            FMA2(acc[4], gd, w4, acc[4]);
            FMA2(acc[5], gd, w5, acc[5]);
            FMA2(acc[6], gd, w6, acc[6]);
            FMA2(acc[7], gd, w7, acc[7]);
        }
        __syncthreads();   // protect w_sh/adj_sh for next chunk
    }

    // reduce softmax denominators
#pragma unroll
    for (int i = 0; i < TI; i++) atomicAdd(&z_sh[i][hB], zp[i]);
    __syncthreads();

#pragma unroll
    for (int k = 0; k < 8; k++) {
        float2 v = *(float2*)&acc[k];
        int ia = 2 * k, ib = 2 * k + 1;
        out[(i0 + ia) * 256 + hC * 32 + lane] = __fdividef(v.x, z_sh[ia][hC]);
        out[(i0 + ib) * 256 + hC * 32 + lane] = __fdividef(v.y, z_sh[ib][hC]);
    }
}

// ---------------------------------------------------------------------------
extern "C" void kernel_launch(void* const* d_in, const int* in_sizes, int n_in,
                              void* d_out, int out_size) {
    const float* H   = (const float*)d_in[0];
    const float* W   = (const float*)d_in[1];
    const float* a   = (const float*)d_in[2];
    const int*   adj = (const int*)d_in[3];
    float*       out = (float*)d_out;

    dim3 gg(OUTF / 64, N_NODES / 64);
    gemm_kernel<<<gg, 256>>>(H, W);
    score_kernel<<<N_NODES / 8, 256>>>(a);
    attn_kernel<<<N_NODES / TI, 256>>>(adj, out);
}

// round 4
// speedup vs baseline: 1.3380x; 1.0777x over previous
#include <cuda_runtime.h>
#include <cstdint>

#define N_NODES 4096
#define OUTF 256
#define NH 8
#define TI 16
#define JC 32
#define NCHUNK (N_NODES / JC)
#define NTHREADS 384            // 8 consumer warps + 4 producer warps

typedef unsigned long long u64;

// Scratch (device globals — no allocation allowed)
__device__ float  g_buf[N_NODES * OUTF];          // g = h @ W^T, [n][h*32+f]
__device__ float4 PL_buf[N_NODES * NH];           // {s_i, exp(s_i), exp(0.2 s_i), 0}
__device__ float4 PR_buf[N_NODES * NH];           // {s_j, exp(s_j), exp(0.2 s_j), 0}

#define PACK2(d, lo, hi) asm("mov.b64 %0, {%1, %2};" : "=l"(d) : "r"(lo), "r"(hi))
#define FMA2(d, a, b, c) asm("fma.rn.f32x2 %0, %1, %2, %3;" : "=l"(d) : "l"(a), "l"(b), "l"(c))
#define LDSV2(a, b, addr) asm volatile("ld.shared.v2.b64 {%0,%1},[%2];" : "=l"(a), "=l"(b) : "r"(addr))

// ---------------------------------------------------------------------------
// Kernel 1: g = h @ W^T   (4096x256 @ 256x256)
// ---------------------------------------------------------------------------
__global__ __launch_bounds__(256) void gemm_kernel(const float* __restrict__ H,
                                                   const float* __restrict__ W) {
    __shared__ float hs[64][32];
    __shared__ float ws[32][68];
    int t  = threadIdx.x;
    int bo = blockIdx.x;
    int bn = blockIdx.y;
    int tx = t & 15, ty = t >> 4;
    float acc[4][4] = {};

    int r = t >> 3, c = (t & 7) << 2;
    for (int k0 = 0; k0 < 256; k0 += 32) {
#pragma unroll
        for (int rr = 0; rr < 64; rr += 32) {
            float4 v = *(const float4*)&H[(bn * 64 + r + rr) * 256 + k0 + c];
            *(float4*)&hs[r + rr][c] = v;
        }
#pragma unroll
        for (int oo = 0; oo < 64; oo += 32) {
            float4 v = *(const float4*)&W[(bo * 64 + r + oo) * 256 + k0 + c];
            ws[c + 0][r + oo] = v.x; ws[c + 1][r + oo] = v.y;
            ws[c + 2][r + oo] = v.z; ws[c + 3][r + oo] = v.w;
        }
        __syncthreads();
#pragma unroll
        for (int k = 0; k < 32; k++) {
            float4 bv = *(const float4*)&ws[k][tx * 4];
            const float* bp = &bv.x;
            float av[4];
#pragma unroll
            for (int i = 0; i < 4; i++) av[i] = hs[ty * 4 + i][k];
#pragma unroll
            for (int i = 0; i < 4; i++)
#pragma unroll
                for (int j = 0; j < 4; j++)
                    acc[i][j] = fmaf(av[i], bp[j], acc[i][j]);
        }
        __syncthreads();
    }
#pragma unroll
    for (int i = 0; i < 4; i++) {
        float4 v = make_float4(acc[i][0], acc[i][1], acc[i][2], acc[i][3]);
        *(float4*)&g_buf[(bn * 64 + ty * 4 + i) * 256 + bo * 64 + tx * 4] = v;
    }
}

// ---------------------------------------------------------------------------
// Kernel 2: per-node scores and exponentials.
// ---------------------------------------------------------------------------
__global__ __launch_bounds__(256) void score_kernel(const float* __restrict__ a) {
    int gw   = (blockIdx.x * 256 + threadIdx.x) >> 5;
    int lane = threadIdx.x & 31;
    if (gw >= N_NODES) return;
    float al = a[lane], ar = a[32 + lane];
#pragma unroll
    for (int h = 0; h < NH; h++) {
        float gv = g_buf[gw * 256 + h * 32 + lane];
        float sl = gv * al, sr = gv * ar;
#pragma unroll
        for (int o = 16; o > 0; o >>= 1) {
            sl += __shfl_xor_sync(0xffffffffu, sl, o);
            sr += __shfl_xor_sync(0xffffffffu, sr, o);
        }
        if (lane == 0) {
            PL_buf[gw * NH + h] = make_float4(sl, expf(sl), expf(0.2f * sl), 0.f);
            PR_buf[gw * NH + h] = make_float4(sr, expf(sr), expf(0.2f * sr), 0.f);
        }
    }
}

// ---------------------------------------------------------------------------
// Kernel 3: warp-specialized fused masked-softmax attention + aggregation.
// Producers (warps 8-11) build chunk c+1's unnormalized softmax weights into
// the spare w_sh buffer (separable exp trick: no MUFU, pl in registers,
// private z accumulators). Consumers (warps 0-7, one per head) run packed
// f32x2 FMAs on chunk c with g pipelined through register halves.
// One __syncthreads per chunk.
// ---------------------------------------------------------------------------
__global__ __launch_bounds__(NTHREADS, 2) void attn_kernel(const int* __restrict__ adj,
                                                           float* __restrict__ out) {
    __shared__ float w_sh[2][JC][NH][20];   // [buf][jj][h][i] (pad 20)
    __shared__ float z_sh[TI][NH];

    const int t  = threadIdx.x;
    const int i0 = blockIdx.x * TI;
    const bool consumer = (t < 256);

    // ---- consumer state ----
    int hC = t >> 5, lane = t & 31;
    const float* grow = &g_buf[hC * 32 + lane];
    unsigned wsb = (unsigned)__cvta_generic_to_shared(&w_sh[0][0][hC & 7][0]);
    u64 acc[8];
    float gA[16], gB[16];

    // ---- producer state ----
    int p = t - 256;                 // 0..127
    int iP = (p >> 3) & 15, hP = p & 7;
    float4 pl;
    const int* adjrow = &adj[(i0 + iP) * N_NODES];
    const float4* prp = &PR_buf[hP];
    float* wbase = &w_sh[0][0][hP][iP];
    float zp = 0.f;

    if (consumer) {
#pragma unroll
        for (int k = 0; k < 8; k++) acc[k] = 0ull;
#pragma unroll
        for (int jj = 0; jj < 16; jj++) gA[jj] = grow[jj * 256];   // chunk0 half0
    } else {
        pl = PL_buf[(i0 + iP) * NH + hP];
        // prime: produce chunk 0 into buf 0
        float* wdst = wbase;
#pragma unroll 8
        for (int jj = 0; jj < JC; jj++) {
            float4 pr = prp[jj * NH];
            int aj = adjrow[jj];
            float s = pl.x + pr.x;
            float w = (s > 0.f) ? pl.y * pr.y : pl.z * pr.z;
            w = aj ? w : 0.f;
            zp += w;
            wdst[jj * (NH * 20)] = w;
        }
    }
    __syncthreads();

    for (int c = 0; c < NCHUNK; c++) {
        if (consumer) {
            int j0 = c * JC;
            unsigned wb = wsb + (c & 1) * (JC * NH * 20 * 4);
            // prefetch half1 g
#pragma unroll
            for (int jj = 0; jj < 16; jj++) gB[jj] = grow[(j0 + 16 + jj) * 256];
            // compute half0
#pragma unroll
            for (int jj = 0; jj < 16; jj++) {
                unsigned gu = __float_as_uint(gA[jj]);
                u64 gd; PACK2(gd, gu, gu);
                unsigned wa = wb + jj * (NH * 20 * 4);
                u64 w0, w1, w2, w3, w4, w5, w6, w7;
                LDSV2(w0, w1, wa);
                LDSV2(w2, w3, wa + 16);
                LDSV2(w4, w5, wa + 32);
                LDSV2(w6, w7, wa + 48);
                FMA2(acc[0], gd, w0, acc[0]);
                FMA2(acc[1], gd, w1, acc[1]);
                FMA2(acc[2], gd, w2, acc[2]);
                FMA2(acc[3], gd, w3, acc[3]);
                FMA2(acc[4], gd, w4, acc[4]);
                FMA2(acc[5], gd, w5, acc[5]);
                FMA2(acc[6], gd, w6, acc[6]);
                FMA2(acc[7], gd, w7, acc[7]);
            }
            // prefetch next chunk half0 (wraps harmlessly on last chunk)
            int j0n = (j0 + JC) & (N_NODES - 1);
#pragma unroll
            for (int jj = 0; jj < 16; jj++) gA[jj] = grow[(j0n + jj) * 256];
            // compute half1
#pragma unroll
            for (int jj = 0; jj < 16; jj++) {
                unsigned gu = __float_as_uint(gB[jj]);
                u64 gd; PACK2(gd, gu, gu);
                unsigned wa = wb + (16 + jj) * (NH * 20 * 4);
                u64 w0, w1, w2, w3, w4, w5, w6, w7;
                LDSV2(w0, w1, wa);
                LDSV2(w2, w3, wa + 16);
                LDSV2(w4, w5, wa + 32);
                LDSV2(w6, w7, wa + 48);
                FMA2(acc[0], gd, w0, acc[0]);
                FMA2(acc[1], gd, w1, acc[1]);
                FMA2(acc[2], gd, w2, acc[2]);
                FMA2(acc[3], gd, w3, acc[3]);
                FMA2(acc[4], gd, w4, acc[4]);
                FMA2(acc[5], gd, w5, acc[5]);
                FMA2(acc[6], gd, w6, acc[6]);
                FMA2(acc[7], gd, w7, acc[7]);
            }
        } else if (c + 1 < NCHUNK) {
            int j0n = (c + 1) * JC;
            float* wdst = wbase + ((c + 1) & 1) * (JC * NH * 20);
            const float4* prc = prp + j0n * NH;
            const int* arc = adjrow + j0n;
#pragma unroll 8
            for (int jj = 0; jj < JC; jj++) {
                float4 pr = prc[jj * NH];
                int aj = arc[jj];
                float s = pl.x + pr.x;
                float w = (s > 0.f) ? pl.y * pr.y : pl.z * pr.z;
                w = aj ? w : 0.f;
                zp += w;
                wdst[jj * (NH * 20)] = w;
            }
        }
        __syncthreads();
    }

    if (!consumer) z_sh[iP][hP] = zp;
    __syncthreads();

    if (consumer) {
#pragma unroll
        for (int k = 0; k < 8; k++) {
            float2 v = *(float2*)&acc[k];
            int ia = 2 * k, ib = 2 * k + 1;
            out[(i0 + ia) * 256 + hC * 32 + lane] = __fdividef(v.x, z_sh[ia][hC]);
            out[(i0 + ib) * 256 + hC * 32 + lane] = __fdividef(v.y, z_sh[ib][hC]);
        }
    }
}

// ---------------------------------------------------------------------------
extern "C" void kernel_launch(void* const* d_in, const int* in_sizes, int n_in,
                              void* d_out, int out_size) {
    const float* H   = (const float*)d_in[0];
    const float* W   = (const float*)d_in[1];
    const float* a   = (const float*)d_in[2];
    const int*   adj = (const int*)d_in[3];
    float*       out = (float*)d_out;

    dim3 gg(OUTF / 64, N_NODES / 64);
    gemm_kernel<<<gg, 256>>>(H, W);
    score_kernel<<<N_NODES / 8, 256>>>(a);
    attn_kernel<<<N_NODES / TI, NTHREADS>>>(adj, out);
}